// round 16
// baseline (speedup 1.0000x reference)
#include <cuda_runtime.h>
#include <cuda_fp16.h>
#include <cstdint>

#define M_ROWS   131072
#define D_ATOM   256
#define D_HID    512
#define D_OUT    256
#define N_ATOMS  256
#define BN_EPS   1e-5

// ---------------- device scratch (allocation-free rule) ----------------
__device__ unsigned short g_zc[(size_t)16384 * 512];   // z split packed (1KB/row)
__device__ unsigned short g_W1c[(size_t)D_HID * 512];  // W1^T packed [n][kchunk][hi32|lo32]
__device__ unsigned short g_W2c[(size_t)D_OUT * 1024]; // W2^T packed
__device__ float g_Y[(size_t)16384 * D_HID];           // Y = z@W1(split) + b1/3 (33.5MB, L2)
__device__ float g_ps[D_HID * 256];                    // [col][b*4+q]
__device__ float g_pq[D_HID * 256];
__device__ float g_s[D_HID];
__device__ float g_t[D_HID];

// ---------------- helpers ----------------
__device__ __forceinline__ uint32_t smem_u32(const void* p) {
    uint32_t a;
    asm("{ .reg .u64 t; cvta.to.shared.u64 t, %1; cvt.u32.u64 %0, t; }" : "=r"(a) : "l"(p));
    return a;
}
__device__ __forceinline__ void cpa16(uint32_t sdst, const void* gsrc) {
    asm volatile("cp.async.cg.shared.global [%0], [%1], 16;" :: "r"(sdst), "l"(gsrc));
}
#define CP_COMMIT() asm volatile("cp.async.commit_group;" ::: "memory")
#define CP_WAIT(n)  asm volatile("cp.async.wait_group %0;" :: "n"(n) : "memory")

__device__ __forceinline__ void ldsm4(uint32_t* r, uint32_t addr) {
    asm volatile("ldmatrix.sync.aligned.m8n8.x4.shared.b16 {%0,%1,%2,%3}, [%4];"
                 : "=r"(r[0]), "=r"(r[1]), "=r"(r[2]), "=r"(r[3]) : "r"(addr));
}
__device__ __forceinline__ void hmma(float* d, const uint32_t* a, uint32_t b0, uint32_t b1) {
    asm volatile("mma.sync.aligned.m16n8k16.row.col.f32.f16.f16.f32 "
                 "{%0,%1,%2,%3},{%4,%5,%6,%7},{%8,%9},{%0,%1,%2,%3};"
                 : "+f"(d[0]), "+f"(d[1]), "+f"(d[2]), "+f"(d[3])
                 : "r"(a[0]), "r"(a[1]), "r"(a[2]), "r"(a[3]), "r"(b0), "r"(b1));
}
__device__ __forceinline__ unsigned short f2h(float x) {
    __half h = __float2half_rn(x);
    return *reinterpret_cast<unsigned short*>(&h);
}
__device__ __forceinline__ float h2f(unsigned short u) {
    __half h = *reinterpret_cast<__half*>(&u);
    return __half2float(h);
}
__device__ __forceinline__ uint32_t pk(unsigned short a, unsigned short b) {
    return (uint32_t)a | ((uint32_t)b << 16);
}

// 2-term split mma over one 128B-row k=32 stage: (ah+al) x bh   (gemmY)
template<int NQ>
__device__ __forceinline__ void mma_stage_2t(uint32_t sa, uint32_t sbm, int wm, int wn,
                                             int lane, float acc[2][NQ * 2][4]) {
    const int xr = lane & 15;
    const int cq = lane >> 4;
    #pragma unroll
    for (int ks = 0; ks < 2; ks++) {
        uint32_t ah[2][4], al[2][4];
        #pragma unroll
        for (int mi = 0; mi < 2; mi++) {
            int row = wm * 32 + mi * 16 + xr;
            uint32_t base = sa + row * 128;
            ldsm4(ah[mi], base + (((ks * 2 + cq) ^ (row & 7)) * 16));
            ldsm4(al[mi], base + (((4 + ks * 2 + cq) ^ (row & 7)) * 16));
        }
        #pragma unroll
        for (int nq = 0; nq < NQ; nq++) {
            int row = wn * (NQ * 16) + nq * 16 + xr;
            uint32_t base = sbm + row * 128;
            uint32_t bh[4];
            ldsm4(bh, base + (((ks * 2 + cq) ^ (row & 7)) * 16));
            #pragma unroll
            for (int mi = 0; mi < 2; mi++)
                #pragma unroll
                for (int p = 0; p < 2; p++) {
                    hmma(acc[mi][nq * 2 + p], ah[mi], bh[p], bh[p + 2]);
                    hmma(acc[mi][nq * 2 + p], al[mi], bh[p], bh[p + 2]);
                }
        }
    }
}

// 1-term mma over one 128B-row k=64 stage (all 8 chunks are hi k-values)
template<int NQ>
__device__ __forceinline__ void mma_stage_1t64(uint32_t sa, uint32_t sbm, int wm, int wn,
                                               int lane, float acc[2][NQ * 2][4]) {
    const int xr = lane & 15;
    const int cq = lane >> 4;
    #pragma unroll
    for (int ks = 0; ks < 4; ks++) {
        uint32_t ah[2][4];
        #pragma unroll
        for (int mi = 0; mi < 2; mi++) {
            int row = wm * 32 + mi * 16 + xr;
            uint32_t base = sa + row * 128;
            ldsm4(ah[mi], base + (((ks * 2 + cq) ^ (row & 7)) * 16));
        }
        #pragma unroll
        for (int nq = 0; nq < NQ; nq++) {
            int row = wn * (NQ * 16) + nq * 16 + xr;
            uint32_t base = sbm + row * 128;
            uint32_t bh[4];
            ldsm4(bh, base + (((ks * 2 + cq) ^ (row & 7)) * 16));
            #pragma unroll
            for (int mi = 0; mi < 2; mi++)
                #pragma unroll
                for (int p = 0; p < 2; p++)
                    hmma(acc[mi][nq * 2 + p], ah[mi], bh[p], bh[p + 2]);
        }
    }
}

// ---------------- kernel: pack + split + transpose weights ----------------
__global__ void __launch_bounds__(256) prepw_kernel(const float* __restrict__ W1,
                                                    const float* __restrict__ W2) {
    int b = blockIdx.x, tid = threadIdx.x;
    if (b < D_HID) {
        int n = b, k = tid;
        float v = W1[(size_t)k * D_HID + n];
        unsigned short hi = f2h(v);
        unsigned short lo = f2h(v - h2f(hi));
        size_t base = ((size_t)n * 8 + (k >> 5)) * 64;
        g_W1c[base + (k & 31)]      = hi;
        g_W1c[base + 32 + (k & 31)] = lo;
    } else {
        int n = b - D_HID;
        #pragma unroll
        for (int q = 0; q < 2; q++) {
            int k = tid + q * 256;
            float v = W2[(size_t)k * D_OUT + n];
            unsigned short hi = f2h(v);
            unsigned short lo = f2h(v - h2f(hi));
            size_t base = ((size_t)n * 16 + (k >> 5)) * 64;
            g_W2c[base + (k & 31)]      = hi;
            g_W2c[base + 32 + (k & 31)] = lo;
        }
    }
}

// ---------------- kernel: split z rows -> packed zc ----------------
__global__ void __launch_bounds__(256) prepz_kernel(const float* __restrict__ z) {
    int tid = threadIdx.x, w = tid >> 5, lane = tid & 31;
    long long r = (long long)blockIdx.x * 8 + w;
    const float4* zr = (const float4*)(z + (size_t)r * D_ATOM);
    int k4 = lane * 2;
    float vs[8];
    #pragma unroll
    for (int q = 0; q < 2; q++) {
        float4 a = zr[k4 + q];
        vs[q * 4 + 0] = a.x; vs[q * 4 + 1] = a.y; vs[q * 4 + 2] = a.z; vs[q * 4 + 3] = a.w;
    }
    unsigned short hb[8], lb[8];
    #pragma unroll
    for (int e = 0; e < 8; e++) {
        hb[e] = f2h(vs[e]);
        lb[e] = f2h(vs[e] - h2f(hb[e]));
    }
    uint4 vh = make_uint4(pk(hb[0], hb[1]), pk(hb[2], hb[3]), pk(hb[4], hb[5]), pk(hb[6], hb[7]));
    uint4 vl = make_uint4(pk(lb[0], lb[1]), pk(lb[2], lb[3]), pk(lb[4], lb[5]), pk(lb[6], lb[7]));
    uint4* g = (uint4*)g_zc;
    size_t base = ((size_t)r * 8 + (lane >> 2)) * 8;
    g[base + (lane & 3)]     = vh;
    g[base + 4 + (lane & 3)] = vl;
}

// ---------------- kernel: Y = z@W1(split) + b1/3 ----------------
#define SA(buf) ((buf) * 16384)
#define SB(buf) (32768 + (buf) * 16384)
#define GY_DYN  65536

__global__ void __launch_bounds__(256) gemmY_kernel(const float* __restrict__ b1) {
    extern __shared__ char smem[];
    __shared__ float sbias[128];

    const int tid = threadIdx.x, lane = tid & 31, wid = tid >> 5;
    const int wm = wid & 3, wn = wid >> 2;
    const int mbase = blockIdx.y * 128;
    const int nbase = blockIdx.x * 128;

    if (tid < 128) sbias[tid] = b1[nbase + tid] * (1.0f / 3.0f);

    {
        const char* gA = (const char*)g_zc;
        const char* gB = (const char*)g_W1c;
        #pragma unroll
        for (int q = 0; q < 4; q++) {
            int u = q * 256 + tid, row = u >> 3, c = u & 7;
            cpa16(smem_u32(smem + SA(0)) + row * 128 + ((c ^ (row & 7)) * 16),
                  gA + ((size_t)(mbase + row) * 8 + 0) * 128 + c * 16);
            cpa16(smem_u32(smem + SB(0)) + row * 128 + ((c ^ (row & 7)) * 16),
                  gB + ((size_t)(nbase + row) * 8 + 0) * 128 + c * 16);
        }
        CP_COMMIT();
    }

    float acc[2][8][4];
    #pragma unroll
    for (int mi = 0; mi < 2; mi++)
        #pragma unroll
        for (int nf = 0; nf < 8; nf++)
            #pragma unroll
            for (int e = 0; e < 4; e++) acc[mi][nf][e] = 0.f;

    #pragma unroll 1
    for (int s = 0; s < 8; s++) {
        if (s + 1 < 8) {
            int nb = (s + 1) & 1;
            const char* gA = (const char*)g_zc;
            const char* gB = (const char*)g_W1c;
            #pragma unroll
            for (int q = 0; q < 4; q++) {
                int u = q * 256 + tid, row = u >> 3, c = u & 7;
                cpa16(smem_u32(smem + SA(nb)) + row * 128 + ((c ^ (row & 7)) * 16),
                      gA + ((size_t)(mbase + row) * 8 + (s + 1)) * 128 + c * 16);
                cpa16(smem_u32(smem + SB(nb)) + row * 128 + ((c ^ (row & 7)) * 16),
                      gB + ((size_t)(nbase + row) * 8 + (s + 1)) * 128 + c * 16);
            }
            CP_COMMIT();
            CP_WAIT(1);
        } else {
            CP_WAIT(0);
        }
        __syncthreads();          // publish stage s BEFORE consumption
        mma_stage_2t<4>(smem_u32(smem + SA(s & 1)), smem_u32(smem + SB(s & 1)), wm, wn, lane, acc);
        __syncthreads();          // all reads done before next overwrite
    }

    const int t4 = lane >> 2, tc = lane & 3;
    #pragma unroll
    for (int mi = 0; mi < 2; mi++)
        #pragma unroll
        for (int nf = 0; nf < 8; nf++) {
            int c0 = wn * 64 + nf * 8 + tc * 2;
            float bb0 = sbias[c0], bb1 = sbias[c0 + 1];
            int colc = c0 >> 2, off = (c0 & 3) * 4;
            #pragma unroll
            for (int rr = 0; rr < 2; rr++) {
                int row = wm * 32 + mi * 16 + t4 + rr * 8;
                *(float2*)(smem + row * 512 + ((colc ^ (row & 7)) * 16) + off) =
                    make_float2(acc[mi][nf][rr * 2] + bb0, acc[mi][nf][rr * 2 + 1] + bb1);
            }
        }
    __syncthreads();
    {
        char* gy = (char*)g_Y;
        #pragma unroll
        for (int q = 0; q < 16; q++) {
            int u = q * 256 + tid, row = u >> 5, c16 = u & 31;
            uint4 v = *(const uint4*)(smem + row * 512 + ((c16 ^ (row & 7)) * 16));
            *(uint4*)(gy + (size_t)(mbase + row) * 2048 + nbase * 4 + c16 * 16) = v;
        }
    }
}

// ---------------- kernel: BN stats (64-col Y slabs + smem idx; indices clamped) ----------------
#define ST_DYN (65536 + 24576)
__global__ void __launch_bounds__(256) bnstat_kernel(const void* __restrict__ tbl) {
    extern __shared__ char smem[];
    float* Ys = (float*)smem;
    int* sIdx = (int*)(smem + 65536);
    __shared__ int s_is64;

    const int tid = threadIdx.x;
    const int b = blockIdx.x >> 3;
    const int c0 = (blockIdx.x & 7) * 64;

    if (tid == 0) {
        const unsigned long long* t64 = (const unsigned long long*)tbl;
        int ok64 = 1;
        #pragma unroll
        for (int i = 0; i < 32; i++) if (t64[i] >= 256ULL) ok64 = 0;
        s_is64 = ok64;
    }
    __syncthreads();

    if (s_is64) {
        const long long* tp = (const long long*)tbl + (size_t)b * 2048 * 3;
        for (int u = tid; u < 6144; u += 256) sIdx[u] = (((int)tp[u]) & 255) << 6;
    } else {
        const int* tp = (const int*)tbl + (size_t)b * 2048 * 3;
        for (int u = tid; u < 6144; u += 256) sIdx[u] = (tp[u] & 255) << 6;
    }

    {
        const float4* src = (const float4*)(g_Y + (size_t)b * 256 * D_HID + c0);
        float4* dst = (float4*)Ys;
        #pragma unroll
        for (int q = 0; q < 16; q++) {
            int u = q * 256 + tid, atom = u >> 4, f = u & 15;
            dst[atom * 16 + f] = src[atom * 128 + f];
        }
    }
    __syncthreads();

    const int c = tid & 63, quar = tid >> 6;
    float s1 = 0.f, s2 = 0.f;
    #pragma unroll 4
    for (int a = quar * 512; a < quar * 512 + 512; a++) {
        int i0 = sIdx[a * 3], i1 = sIdx[a * 3 + 1], i2 = sIdx[a * 3 + 2];
        float h = Ys[i0 + c] + Ys[i1 + c] + Ys[i2 + c];
        s1 += h;
        s2 = fmaf(h, h, s2);
    }
    g_ps[(size_t)(c0 + c) * 256 + b * 4 + quar] = s1;
    g_pq[(size_t)(c0 + c) * 256 + b * 4 + quar] = s2;
}

// ---------------- kernel: finalize BN affine ----------------
__global__ void __launch_bounds__(512) bnfin_kernel(const float* __restrict__ gamma,
                                                    const float* __restrict__ beta) {
    int c = threadIdx.x;
    double a1 = 0.0, a2 = 0.0;
    #pragma unroll 4
    for (int i = 0; i < 256; i++) {
        a1 += (double)g_ps[(size_t)c * 256 + i];
        a2 += (double)g_pq[(size_t)c * 256 + i];
    }
    double mean = a1 / (double)M_ROWS;
    double var  = a2 / (double)M_ROWS - mean * mean;
    float sv = (float)((double)gamma[c] / sqrt(var + (double)BN_EPS));
    g_s[c] = sv;
    g_t[c] = beta[c] - (float)mean * sv;
}

// ---------------- kernel: GEMM2  out = relu(affine(gatherY))@W2h + b2 ----------------
// K=512 in 8 stages of k=64 (hi-only 128B rows). 1-term mma. Race-free pipeline:
// B triple-buffered cp.async, wait -> barrier -> consume. A gathered directly
// from L2 (synchronous LDG), hi-split only. Half the barriers and half the B
// traffic of the k=32 version; identical k-step order -> identical rounding.
// grid (1024), 512 threads (16 warps 4m x 4n), tile 128x256.
// dyn smem: A[2][16KB] @0, B[3][32KB] @32KB = 128KB.
#define G2A(buf)  ((buf) * 16384)
#define G2B(buf)  (32768 + (buf) * 32768)
#define G2_DYN    131072

__global__ void __launch_bounds__(512, 1) gemm2_kernel(const void* __restrict__ tbl,
                                                       const float* __restrict__ b2,
                                                       float* __restrict__ out) {
    extern __shared__ char smem[];
    __shared__ float ss[D_HID], tt[D_HID], b2s[256];
    __shared__ int sI0[128], sI1[128], sI2[128];
    __shared__ int s_is64;

    const int tid = threadIdx.x, lane = tid & 31, wid = tid >> 5;
    const int wm = wid & 3, wn = wid >> 2;
    const int mbase = blockIdx.x * 128;
    const int batch = blockIdx.x >> 4;

    if (tid == 0) {
        const unsigned long long* t64 = (const unsigned long long*)tbl;
        int ok64 = 1;
        #pragma unroll
        for (int i = 0; i < 32; i++) if (t64[i] >= 256ULL) ok64 = 0;
        s_is64 = ok64;
    }
    if (tid < 256) {
        ss[tid]       = g_s[tid];
        ss[tid + 256] = g_s[tid + 256];
        tt[tid]       = g_t[tid];
        tt[tid + 256] = g_t[tid + 256];
        b2s[tid]      = b2[tid];
    }
    __syncthreads();
    if (tid < 128) {
        long long r = (long long)mbase + tid;
        int i0, i1, i2;
        if (s_is64) {
            const long long* tp = (const long long*)tbl + r * 3;
            i0 = (int)tp[0]; i1 = (int)tp[1]; i2 = (int)tp[2];
        } else {
            const int* tp = (const int*)tbl + r * 3;
            i0 = tp[0]; i1 = tp[1]; i2 = tp[2];
        }
        sI0[tid] = i0 & 255;
        sI1[tid] = i1 & 255;
        sI2[tid] = i2 & 255;
    }
    __syncthreads();

    const float* Yb = g_Y + (size_t)batch * 256 * D_HID;

    // stage B for k=64 stage s: 256 rows x 8 chunks; chunk c sources the hi half
    // of kchunk (2s + (c>>2)) at inner offset (c&3)*16
    auto issueB = [&](int s, int buf) {
        const char* gB = (const char*)g_W2c;
        #pragma unroll
        for (int q = 0; q < 4; q++) {
            int u = q * 512 + tid, row = u >> 3, c = u & 7;
            int kc = 2 * s + (c >> 2);
            cpa16(smem_u32(smem + G2B(buf)) + row * 128 + ((c ^ (row & 7)) * 16),
                  gB + ((size_t)row * 16 + kc) * 128 + (c & 3) * 16);
        }
        CP_COMMIT();
    };

    // build one k=64 A stage by direct L2 gather; 16 hi values per thread in
    // two 8-value halves (keeps live registers at the k=32 version's level)
    auto buildA = [&](int s, int buf) {
        const int row = tid >> 2, seg = tid & 3;
        const int i0 = sI0[row], i1 = sI1[row], i2 = sI2[row];
        #pragma unroll
        for (int h = 0; h < 2; h++) {
            const int ko = s * 64 + seg * 16 + h * 8;
            const float4* p0 = (const float4*)(Yb + (size_t)i0 * D_HID + ko);
            const float4* p1 = (const float4*)(Yb + (size_t)i1 * D_HID + ko);
            const float4* p2 = (const float4*)(Yb + (size_t)i2 * D_HID + ko);
            float4 a0 = p0[0], a1 = p0[1];
            float4 b0 = p1[0], b1v = p1[1];
            float4 c0v = p2[0], c1 = p2[1];
            float f[8];
            f[0] = a0.x + b0.x + c0v.x;  f[1] = a0.y + b0.y + c0v.y;
            f[2] = a0.z + b0.z + c0v.z;  f[3] = a0.w + b0.w + c0v.w;
            f[4] = a1.x + b1v.x + c1.x;  f[5] = a1.y + b1v.y + c1.y;
            f[6] = a1.z + b1v.z + c1.z;  f[7] = a1.w + b1v.w + c1.w;
            unsigned short hb[8];
            #pragma unroll
            for (int e = 0; e < 8; e++)
                hb[e] = f2h(fmaxf(fmaf(f[e], ss[ko + e], tt[ko + e]), 0.f));
            int chunk = seg * 2 + h;
            *(uint4*)(smem + G2A(buf) + row * 128 + ((chunk ^ (row & 7)) * 16)) =
                make_uint4(pk(hb[0], hb[1]), pk(hb[2], hb[3]), pk(hb[4], hb[5]), pk(hb[6], hb[7]));
        }
    };

    // prologue: 3 B groups in flight; A(0) built; B(0),B(1),A(0) published
    issueB(0, 0);
    issueB(1, 1);
    issueB(2, 2);
    buildA(0, 0);
    CP_WAIT(1);            // own groups 0 and 1 complete
    __syncthreads();       // publish B(0), B(1), A(0)

    float acc[2][8][4];
    #pragma unroll
    for (int mi = 0; mi < 2; mi++)
        #pragma unroll
        for (int nf = 0; nf < 8; nf++)
            #pragma unroll
            for (int e = 0; e < 4; e++) acc[mi][nf][e] = 0.f;

    // invariant at iter s: B(s), B(s+1), A(s) published; groups {s+2,[s+3]} in flight
    #pragma unroll 1
    for (int s = 0; s < 8; s++) {
        mma_stage_1t64<4>(smem_u32(smem + G2A(s & 1)), smem_u32(smem + G2B(s % 3)), wm, wn, lane, acc);
        if (s + 1 < 8) buildA(s + 1, (s + 1) & 1);      // reads published data only
        __syncthreads();                                 // readers of B(s%3) done; A(s+1) staged
        if (s + 3 < 8) issueB(s + 3, s % 3);             // safe overwrite (post-barrier)
        if (s < 5) { CP_WAIT(1); }                       // complete own group s+2
        else       { CP_WAIT(0); }                       // tail drain
        __syncthreads();                                 // publish B(s+2) + A(s+1)
    }

    // epilogue: +b2, stage fp32 (1KB rows, swizzled), coalesced out write
    const int t4 = lane >> 2, tc = lane & 3;
    #pragma unroll
    for (int mi = 0; mi < 2; mi++)
        #pragma unroll
        for (int nf = 0; nf < 8; nf++) {
            int c0 = wn * 64 + nf * 8 + tc * 2;
            float bb0 = b2s[c0], bb1 = b2s[c0 + 1];
            int colc = c0 >> 2, off = (c0 & 3) * 4;
            #pragma unroll
            for (int rr = 0; rr < 2; rr++) {
                int row = wm * 32 + mi * 16 + t4 + rr * 8;
                *(float2*)(smem + row * 1024 + ((colc ^ (row & 7)) * 16) + off) =
                    make_float2(acc[mi][nf][rr * 2] + bb0, acc[mi][nf][rr * 2 + 1] + bb1);
            }
        }
    __syncthreads();
    {
        char* go = (char*)out;
        #pragma unroll
        for (int q = 0; q < 16; q++) {
            int u = q * 512 + tid, row = u >> 6, c16 = u & 63;
            uint4 v = *(const uint4*)(smem + row * 1024 + ((c16 ^ (row & 7)) * 16));
            *(uint4*)(go + (size_t)(mbase + row) * 1024 + c16 * 16) = v;
        }
    }
}

// ---------------- launch ----------------
extern "C" void kernel_launch(void* const* d_in, const int* in_sizes, int n_in,
                              void* d_out, int out_size) {
    // resolve inputs by size signature (identity under canonical order)
    int i_z = -1, i_tb = -1, i_w1 = -1, i_b1 = -1, i_g = -1, i_be = -1, i_w2 = -1, i_b2 = -1;
    for (int i = 0; i < n_in; i++) {
        int s = in_sizes[i];
        if      (s == 4194304 && i_z  < 0) i_z  = i;
        else if (s == 393216  && i_tb < 0) i_tb = i;
        else if (s == 131072) { if (i_w1 < 0) i_w1 = i; else if (i_w2 < 0) i_w2 = i; }
        else if (s == 512)    { if (i_b1 < 0) i_b1 = i; else if (i_g < 0) i_g = i; else if (i_be < 0) i_be = i; }
        else if (s == 256     && i_b2 < 0) i_b2 = i;
    }
    if (i_z < 0 || i_tb < 0 || i_w1 < 0 || i_b1 < 0 || i_g < 0 || i_be < 0 || i_w2 < 0 || i_b2 < 0) {
        i_z = 0; i_tb = 1; i_w1 = 2; i_b1 = 3; i_g = 4; i_be = 5; i_w2 = 6; i_b2 = 7;
    }
    const float* z     = (const float*)d_in[i_z];
    const void*  tbl   = d_in[i_tb];
    const float* W1    = (const float*)d_in[i_w1];
    const float* b1    = (const float*)d_in[i_b1];
    const float* gamma = (const float*)d_in[i_g];
    const float* beta  = (const float*)d_in[i_be];
    const float* W2    = (const float*)d_in[i_w2];
    const float* b2    = (const float*)d_in[i_b2];
    float* out = (float*)d_out;

    cudaFuncSetAttribute(gemmY_kernel,  cudaFuncAttributeMaxDynamicSharedMemorySize, GY_DYN);
    cudaFuncSetAttribute(bnstat_kernel, cudaFuncAttributeMaxDynamicSharedMemorySize, ST_DYN);
    cudaFuncSetAttribute(gemm2_kernel,  cudaFuncAttributeMaxDynamicSharedMemorySize, G2_DYN);

    prepw_kernel<<<D_HID + D_OUT, 256>>>(W1, W2);
    prepz_kernel<<<16384 / 8, 256>>>(z);
    gemmY_kernel<<<dim3(4, 128), 256, GY_DYN>>>(b1);
    bnstat_kernel<<<512, 256, ST_DYN>>>(tbl);
    bnfin_kernel<<<1, 512>>>(gamma, beta);
    gemm2_kernel<<<1024, 512, G2_DYN>>>(tbl, b2, out);
}

// round 17
// speedup vs baseline: 1.0810x; 1.0810x over previous
#include <cuda_runtime.h>
#include <cuda_fp16.h>
#include <cstdint>

#define M_ROWS   131072
#define D_ATOM   256
#define D_HID    512
#define D_OUT    256
#define N_ATOMS  256
#define BN_EPS   1e-5

// ---------------- device scratch (allocation-free rule) ----------------
__device__ unsigned short g_zc[(size_t)16384 * 512];   // z split packed (1KB/row)
__device__ unsigned short g_W1c[(size_t)D_HID * 512];  // W1^T packed [n][kchunk][hi32|lo32]
__device__ unsigned short g_W2c[(size_t)D_OUT * 1024]; // W2^T packed
__device__ float g_Y[(size_t)16384 * D_HID];           // Y = z@W1(split) + b1/3 (33.5MB, L2)
__device__ float g_ps[D_HID * 256];                    // [col][b*4+q]
__device__ float g_pq[D_HID * 256];
__device__ float g_s[D_HID];
__device__ float g_t[D_HID];

// ---------------- helpers ----------------
__device__ __forceinline__ uint32_t smem_u32(const void* p) {
    uint32_t a;
    asm("{ .reg .u64 t; cvta.to.shared.u64 t, %1; cvt.u32.u64 %0, t; }" : "=r"(a) : "l"(p));
    return a;
}
__device__ __forceinline__ void cpa16(uint32_t sdst, const void* gsrc) {
    asm volatile("cp.async.cg.shared.global [%0], [%1], 16;" :: "r"(sdst), "l"(gsrc));
}
#define CP_COMMIT() asm volatile("cp.async.commit_group;" ::: "memory")
#define CP_WAIT(n)  asm volatile("cp.async.wait_group %0;" :: "n"(n) : "memory")

__device__ __forceinline__ void ldsm4(uint32_t* r, uint32_t addr) {
    asm volatile("ldmatrix.sync.aligned.m8n8.x4.shared.b16 {%0,%1,%2,%3}, [%4];"
                 : "=r"(r[0]), "=r"(r[1]), "=r"(r[2]), "=r"(r[3]) : "r"(addr));
}
__device__ __forceinline__ void hmma(float* d, const uint32_t* a, uint32_t b0, uint32_t b1) {
    asm volatile("mma.sync.aligned.m16n8k16.row.col.f32.f16.f16.f32 "
                 "{%0,%1,%2,%3},{%4,%5,%6,%7},{%8,%9},{%0,%1,%2,%3};"
                 : "+f"(d[0]), "+f"(d[1]), "+f"(d[2]), "+f"(d[3])
                 : "r"(a[0]), "r"(a[1]), "r"(a[2]), "r"(a[3]), "r"(b0), "r"(b1));
}
__device__ __forceinline__ unsigned short f2h(float x) {
    __half h = __float2half_rn(x);
    return *reinterpret_cast<unsigned short*>(&h);
}
__device__ __forceinline__ float h2f(unsigned short u) {
    __half h = *reinterpret_cast<__half*>(&u);
    return __half2float(h);
}
__device__ __forceinline__ uint32_t pk(unsigned short a, unsigned short b) {
    return (uint32_t)a | ((uint32_t)b << 16);
}

// 2-term split mma over one 128B-row k=32 stage: (ah+al) x bh   (gemmY)
template<int NQ>
__device__ __forceinline__ void mma_stage_2t(uint32_t sa, uint32_t sbm, int wm, int wn,
                                             int lane, float acc[2][NQ * 2][4]) {
    const int xr = lane & 15;
    const int cq = lane >> 4;
    #pragma unroll
    for (int ks = 0; ks < 2; ks++) {
        uint32_t ah[2][4], al[2][4];
        #pragma unroll
        for (int mi = 0; mi < 2; mi++) {
            int row = wm * 32 + mi * 16 + xr;
            uint32_t base = sa + row * 128;
            ldsm4(ah[mi], base + (((ks * 2 + cq) ^ (row & 7)) * 16));
            ldsm4(al[mi], base + (((4 + ks * 2 + cq) ^ (row & 7)) * 16));
        }
        #pragma unroll
        for (int nq = 0; nq < NQ; nq++) {
            int row = wn * (NQ * 16) + nq * 16 + xr;
            uint32_t base = sbm + row * 128;
            uint32_t bh[4];
            ldsm4(bh, base + (((ks * 2 + cq) ^ (row & 7)) * 16));
            #pragma unroll
            for (int mi = 0; mi < 2; mi++)
                #pragma unroll
                for (int p = 0; p < 2; p++) {
                    hmma(acc[mi][nq * 2 + p], ah[mi], bh[p], bh[p + 2]);
                    hmma(acc[mi][nq * 2 + p], al[mi], bh[p], bh[p + 2]);
                }
        }
    }
}

// 1-term mma over one 128B-row k=32 stage: ah x bh
template<int NQ>
__device__ __forceinline__ void mma_stage_1t(uint32_t sa, uint32_t sbm, int wm, int wn,
                                             int lane, float acc[2][NQ * 2][4]) {
    const int xr = lane & 15;
    const int cq = lane >> 4;
    #pragma unroll
    for (int ks = 0; ks < 2; ks++) {
        uint32_t ah[2][4];
        #pragma unroll
        for (int mi = 0; mi < 2; mi++) {
            int row = wm * 32 + mi * 16 + xr;
            uint32_t base = sa + row * 128;
            ldsm4(ah[mi], base + (((ks * 2 + cq) ^ (row & 7)) * 16));
        }
        #pragma unroll
        for (int nq = 0; nq < NQ; nq++) {
            int row = wn * (NQ * 16) + nq * 16 + xr;
            uint32_t base = sbm + row * 128;
            uint32_t bh[4];
            ldsm4(bh, base + (((ks * 2 + cq) ^ (row & 7)) * 16));
            #pragma unroll
            for (int mi = 0; mi < 2; mi++)
                #pragma unroll
                for (int p = 0; p < 2; p++)
                    hmma(acc[mi][nq * 2 + p], ah[mi], bh[p], bh[p + 2]);
        }
    }
}

// ---------------- kernel: pack + split + transpose weights ----------------
__global__ void __launch_bounds__(256) prepw_kernel(const float* __restrict__ W1,
                                                    const float* __restrict__ W2) {
    int b = blockIdx.x, tid = threadIdx.x;
    if (b < D_HID) {
        int n = b, k = tid;
        float v = W1[(size_t)k * D_HID + n];
        unsigned short hi = f2h(v);
        unsigned short lo = f2h(v - h2f(hi));
        size_t base = ((size_t)n * 8 + (k >> 5)) * 64;
        g_W1c[base + (k & 31)]      = hi;
        g_W1c[base + 32 + (k & 31)] = lo;
    } else {
        int n = b - D_HID;
        #pragma unroll
        for (int q = 0; q < 2; q++) {
            int k = tid + q * 256;
            float v = W2[(size_t)k * D_OUT + n];
            unsigned short hi = f2h(v);
            unsigned short lo = f2h(v - h2f(hi));
            size_t base = ((size_t)n * 16 + (k >> 5)) * 64;
            g_W2c[base + (k & 31)]      = hi;
            g_W2c[base + 32 + (k & 31)] = lo;
        }
    }
}

// ---------------- kernel: split z rows -> packed zc ----------------
__global__ void __launch_bounds__(256) prepz_kernel(const float* __restrict__ z) {
    int tid = threadIdx.x, w = tid >> 5, lane = tid & 31;
    long long r = (long long)blockIdx.x * 8 + w;
    const float4* zr = (const float4*)(z + (size_t)r * D_ATOM);
    int k4 = lane * 2;
    float vs[8];
    #pragma unroll
    for (int q = 0; q < 2; q++) {
        float4 a = zr[k4 + q];
        vs[q * 4 + 0] = a.x; vs[q * 4 + 1] = a.y; vs[q * 4 + 2] = a.z; vs[q * 4 + 3] = a.w;
    }
    unsigned short hb[8], lb[8];
    #pragma unroll
    for (int e = 0; e < 8; e++) {
        hb[e] = f2h(vs[e]);
        lb[e] = f2h(vs[e] - h2f(hb[e]));
    }
    uint4 vh = make_uint4(pk(hb[0], hb[1]), pk(hb[2], hb[3]), pk(hb[4], hb[5]), pk(hb[6], hb[7]));
    uint4 vl = make_uint4(pk(lb[0], lb[1]), pk(lb[2], lb[3]), pk(lb[4], lb[5]), pk(lb[6], lb[7]));
    uint4* g = (uint4*)g_zc;
    size_t base = ((size_t)r * 8 + (lane >> 2)) * 8;
    g[base + (lane & 3)]     = vh;
    g[base + 4 + (lane & 3)] = vl;
}

// ---------------- kernel: Y = z@W1(split) + b1/3 ----------------
#define SA(buf) ((buf) * 16384)
#define SB(buf) (32768 + (buf) * 16384)
#define GY_DYN  65536

__global__ void __launch_bounds__(256) gemmY_kernel(const float* __restrict__ b1) {
    extern __shared__ char smem[];
    __shared__ float sbias[128];

    const int tid = threadIdx.x, lane = tid & 31, wid = tid >> 5;
    const int wm = wid & 3, wn = wid >> 2;
    const int mbase = blockIdx.y * 128;
    const int nbase = blockIdx.x * 128;

    if (tid < 128) sbias[tid] = b1[nbase + tid] * (1.0f / 3.0f);

    {
        const char* gA = (const char*)g_zc;
        const char* gB = (const char*)g_W1c;
        #pragma unroll
        for (int q = 0; q < 4; q++) {
            int u = q * 256 + tid, row = u >> 3, c = u & 7;
            cpa16(smem_u32(smem + SA(0)) + row * 128 + ((c ^ (row & 7)) * 16),
                  gA + ((size_t)(mbase + row) * 8 + 0) * 128 + c * 16);
            cpa16(smem_u32(smem + SB(0)) + row * 128 + ((c ^ (row & 7)) * 16),
                  gB + ((size_t)(nbase + row) * 8 + 0) * 128 + c * 16);
        }
        CP_COMMIT();
    }

    float acc[2][8][4];
    #pragma unroll
    for (int mi = 0; mi < 2; mi++)
        #pragma unroll
        for (int nf = 0; nf < 8; nf++)
            #pragma unroll
            for (int e = 0; e < 4; e++) acc[mi][nf][e] = 0.f;

    #pragma unroll 1
    for (int s = 0; s < 8; s++) {
        if (s + 1 < 8) {
            int nb = (s + 1) & 1;
            const char* gA = (const char*)g_zc;
            const char* gB = (const char*)g_W1c;
            #pragma unroll
            for (int q = 0; q < 4; q++) {
                int u = q * 256 + tid, row = u >> 3, c = u & 7;
                cpa16(smem_u32(smem + SA(nb)) + row * 128 + ((c ^ (row & 7)) * 16),
                      gA + ((size_t)(mbase + row) * 8 + (s + 1)) * 128 + c * 16);
                cpa16(smem_u32(smem + SB(nb)) + row * 128 + ((c ^ (row & 7)) * 16),
                      gB + ((size_t)(nbase + row) * 8 + (s + 1)) * 128 + c * 16);
            }
            CP_COMMIT();
            CP_WAIT(1);
        } else {
            CP_WAIT(0);
        }
        __syncthreads();          // publish stage s BEFORE consumption
        mma_stage_2t<4>(smem_u32(smem + SA(s & 1)), smem_u32(smem + SB(s & 1)), wm, wn, lane, acc);
        __syncthreads();          // all reads done before next overwrite
    }

    const int t4 = lane >> 2, tc = lane & 3;
    #pragma unroll
    for (int mi = 0; mi < 2; mi++)
        #pragma unroll
        for (int nf = 0; nf < 8; nf++) {
            int c0 = wn * 64 + nf * 8 + tc * 2;
            float bb0 = sbias[c0], bb1 = sbias[c0 + 1];
            int colc = c0 >> 2, off = (c0 & 3) * 4;
            #pragma unroll
            for (int rr = 0; rr < 2; rr++) {
                int row = wm * 32 + mi * 16 + t4 + rr * 8;
                *(float2*)(smem + row * 512 + ((colc ^ (row & 7)) * 16) + off) =
                    make_float2(acc[mi][nf][rr * 2] + bb0, acc[mi][nf][rr * 2 + 1] + bb1);
            }
        }
    __syncthreads();
    {
        char* gy = (char*)g_Y;
        #pragma unroll
        for (int q = 0; q < 16; q++) {
            int u = q * 256 + tid, row = u >> 5, c16 = u & 31;
            uint4 v = *(const uint4*)(smem + row * 512 + ((c16 ^ (row & 7)) * 16));
            *(uint4*)(gy + (size_t)(mbase + row) * 2048 + nbase * 4 + c16 * 16) = v;
        }
    }
}

// ---------------- kernel: BN stats (64-col Y slabs + smem idx; indices clamped) ----------------
#define ST_DYN (65536 + 24576)
__global__ void __launch_bounds__(256) bnstat_kernel(const void* __restrict__ tbl) {
    extern __shared__ char smem[];
    float* Ys = (float*)smem;
    int* sIdx = (int*)(smem + 65536);
    __shared__ int s_is64;

    const int tid = threadIdx.x;
    const int b = blockIdx.x >> 3;
    const int c0 = (blockIdx.x & 7) * 64;

    if (tid == 0) {
        const unsigned long long* t64 = (const unsigned long long*)tbl;
        int ok64 = 1;
        #pragma unroll
        for (int i = 0; i < 32; i++) if (t64[i] >= 256ULL) ok64 = 0;
        s_is64 = ok64;
    }
    __syncthreads();

    if (s_is64) {
        const long long* tp = (const long long*)tbl + (size_t)b * 2048 * 3;
        for (int u = tid; u < 6144; u += 256) sIdx[u] = (((int)tp[u]) & 255) << 6;
    } else {
        const int* tp = (const int*)tbl + (size_t)b * 2048 * 3;
        for (int u = tid; u < 6144; u += 256) sIdx[u] = (tp[u] & 255) << 6;
    }

    {
        const float4* src = (const float4*)(g_Y + (size_t)b * 256 * D_HID + c0);
        float4* dst = (float4*)Ys;
        #pragma unroll
        for (int q = 0; q < 16; q++) {
            int u = q * 256 + tid, atom = u >> 4, f = u & 15;
            dst[atom * 16 + f] = src[atom * 128 + f];
        }
    }
    __syncthreads();

    const int c = tid & 63, quar = tid >> 6;
    float s1 = 0.f, s2 = 0.f;
    #pragma unroll 4
    for (int a = quar * 512; a < quar * 512 + 512; a++) {
        int i0 = sIdx[a * 3], i1 = sIdx[a * 3 + 1], i2 = sIdx[a * 3 + 2];
        float h = Ys[i0 + c] + Ys[i1 + c] + Ys[i2 + c];
        s1 += h;
        s2 = fmaf(h, h, s2);
    }
    g_ps[(size_t)(c0 + c) * 256 + b * 4 + quar] = s1;
    g_pq[(size_t)(c0 + c) * 256 + b * 4 + quar] = s2;
}

// ---------------- kernel: finalize BN affine ----------------
__global__ void __launch_bounds__(512) bnfin_kernel(const float* __restrict__ gamma,
                                                    const float* __restrict__ beta) {
    int c = threadIdx.x;
    double a1 = 0.0, a2 = 0.0;
    #pragma unroll 4
    for (int i = 0; i < 256; i++) {
        a1 += (double)g_ps[(size_t)c * 256 + i];
        a2 += (double)g_pq[(size_t)c * 256 + i];
    }
    double mean = a1 / (double)M_ROWS;
    double var  = a2 / (double)M_ROWS - mean * mean;
    float sv = (float)((double)gamma[c] / sqrt(var + (double)BN_EPS));
    g_s[c] = sv;
    g_t[c] = beta[c] - (float)mean * sv;
}

// ---------------- kernel: GEMM2  out = relu(affine(gatherY))@W2h + b2 ----------------
// Tile 64x256, 256 threads (8 warps: 2m x 4n), 2 CTAs/SM. K=512 in 16 stages of 32.
// 1-term mma. Race-free: B double-buffered cp.async with wait -> barrier -> consume;
// A by direct L2 gather. Per-row gather still happens exactly once (tileN=256).
// grid (2048). dyn smem: A[2][8KB] @0, B[2][32KB] @16KB = 80KB -> 2 CTAs/SM.
#define G2A(buf)  ((buf) * 8192)
#define G2B(buf)  (16384 + (buf) * 32768)
#define G2_DYN    81920

__global__ void __launch_bounds__(256, 2) gemm2_kernel(const void* __restrict__ tbl,
                                                       const float* __restrict__ b2,
                                                       float* __restrict__ out) {
    extern __shared__ char smem[];
    __shared__ float ss[D_HID], tt[D_HID], b2s[256];
    __shared__ int sI0[64], sI1[64], sI2[64];
    __shared__ int s_is64;

    const int tid = threadIdx.x, lane = tid & 31, wid = tid >> 5;
    const int wm = wid & 1, wn = wid >> 1;
    const int mbase = blockIdx.x * 64;
    const int batch = blockIdx.x >> 5;             // 32 m-tiles per batch

    if (tid == 0) {
        const unsigned long long* t64 = (const unsigned long long*)tbl;
        int ok64 = 1;
        #pragma unroll
        for (int i = 0; i < 32; i++) if (t64[i] >= 256ULL) ok64 = 0;
        s_is64 = ok64;
    }
    {
        ss[tid]       = g_s[tid];
        ss[tid + 256] = g_s[tid + 256];
        tt[tid]       = g_t[tid];
        tt[tid + 256] = g_t[tid + 256];
        b2s[tid]      = b2[tid];
    }
    __syncthreads();
    if (tid < 64) {
        long long r = (long long)mbase + tid;
        int i0, i1, i2;
        if (s_is64) {
            const long long* tp = (const long long*)tbl + r * 3;
            i0 = (int)tp[0]; i1 = (int)tp[1]; i2 = (int)tp[2];
        } else {
            const int* tp = (const int*)tbl + r * 3;
            i0 = tp[0]; i1 = tp[1]; i2 = tp[2];
        }
        sI0[tid] = i0 & 255;
        sI1[tid] = i1 & 255;
        sI2[tid] = i2 & 255;
    }
    __syncthreads();

    const float* Yb = g_Y + (size_t)batch * 256 * D_HID;

    // stage B: 256 rows x 8 chunks = 2048 units, 8 per thread
    auto issueB = [&](int s, int buf) {
        const char* gB = (const char*)g_W2c;
        #pragma unroll
        for (int q = 0; q < 8; q++) {
            int u = q * 256 + tid, row = u >> 3, c = u & 7;
            cpa16(smem_u32(smem + G2B(buf)) + row * 128 + ((c ^ (row & 7)) * 16),
                  gB + ((size_t)row * 16 + s) * 128 + c * 16);
        }
        CP_COMMIT();
    };

    // build one A stage by direct L2 gather (8 k-values per thread; 64 rows x 4 seg)
    auto buildA = [&](int s, int buf) {
        const int row = tid >> 2, seg = tid & 3;
        const int i0 = sI0[row], i1 = sI1[row], i2 = sI2[row];
        const int ko = s * 32 + seg * 8;
        const float4* p0 = (const float4*)(Yb + (size_t)i0 * D_HID + ko);
        const float4* p1 = (const float4*)(Yb + (size_t)i1 * D_HID + ko);
        const float4* p2 = (const float4*)(Yb + (size_t)i2 * D_HID + ko);
        float4 a0 = p0[0], a1 = p0[1];
        float4 b0 = p1[0], b1v = p1[1];
        float4 c0v = p2[0], c1 = p2[1];
        float f[8];
        f[0] = a0.x + b0.x + c0v.x;  f[1] = a0.y + b0.y + c0v.y;
        f[2] = a0.z + b0.z + c0v.z;  f[3] = a0.w + b0.w + c0v.w;
        f[4] = a1.x + b1v.x + c1.x;  f[5] = a1.y + b1v.y + c1.y;
        f[6] = a1.z + b1v.z + c1.z;  f[7] = a1.w + b1v.w + c1.w;
        unsigned short hb[8], lb[8];
        #pragma unroll
        for (int e = 0; e < 8; e++) {
            float y = fmaxf(fmaf(f[e], ss[ko + e], tt[ko + e]), 0.f);
            hb[e] = f2h(y);
            lb[e] = f2h(y - h2f(hb[e]));
        }
        uint4 vh = make_uint4(pk(hb[0], hb[1]), pk(hb[2], hb[3]), pk(hb[4], hb[5]), pk(hb[6], hb[7]));
        uint4 vl = make_uint4(pk(lb[0], lb[1]), pk(lb[2], lb[3]), pk(lb[4], lb[5]), pk(lb[6], lb[7]));
        *(uint4*)(smem + G2A(buf) + row * 128 + ((seg ^ (row & 7)) * 16)) = vh;
        *(uint4*)(smem + G2A(buf) + row * 128 + (((seg + 4) ^ (row & 7)) * 16)) = vl;
    };

    // prologue: B(0), B(1) in flight; A(0) built; B(0), A(0) published
    issueB(0, 0);
    issueB(1, 1);
    buildA(0, 0);
    CP_WAIT(1);            // B(0) complete
    __syncthreads();       // publish B(0), A(0)

    float acc[2][8][4];
    #pragma unroll
    for (int mi = 0; mi < 2; mi++)
        #pragma unroll
        for (int nf = 0; nf < 8; nf++)
            #pragma unroll
            for (int e = 0; e < 4; e++) acc[mi][nf][e] = 0.f;

    // invariant at iter s: B(s), A(s) published; B(s+1) [+B(s+2) after issue] in flight
    #pragma unroll 1
    for (int s = 0; s < 16; s++) {
        mma_stage_1t<4>(smem_u32(smem + G2A(s & 1)), smem_u32(smem + G2B(s & 1)), wm, wn, lane, acc);
        if (s + 1 < 16) buildA(s + 1, (s + 1) & 1);     // reads published data only
        __syncthreads();                                 // readers of B(s&1) done; A(s+1) staged
        if (s + 2 < 16) issueB(s + 2, s & 1);            // safe overwrite (post-barrier)
        if (s + 2 < 16)      { CP_WAIT(1); }             // complete B(s+1)
        else if (s + 1 < 16) { CP_WAIT(0); }             // tail: complete B(s+1)
        __syncthreads();                                 // publish B(s+1) + A(s+1)
    }

    // epilogue: +b2, stage fp32 (1KB rows, swizzled), coalesced out write
    const int t4 = lane >> 2, tc = lane & 3;
    #pragma unroll
    for (int mi = 0; mi < 2; mi++)
        #pragma unroll
        for (int nf = 0; nf < 8; nf++) {
            int c0 = wn * 64 + nf * 8 + tc * 2;
            float bb0 = b2s[c0], bb1 = b2s[c0 + 1];
            int colc = c0 >> 2, off = (c0 & 3) * 4;
            #pragma unroll
            for (int rr = 0; rr < 2; rr++) {
                int row = wm * 32 + mi * 16 + t4 + rr * 8;
                *(float2*)(smem + row * 1024 + ((colc ^ (row & 7)) * 16) + off) =
                    make_float2(acc[mi][nf][rr * 2] + bb0, acc[mi][nf][rr * 2 + 1] + bb1);
            }
        }
    __syncthreads();
    {
        char* go = (char*)out;
        #pragma unroll
        for (int q = 0; q < 16; q++) {
            int u = q * 256 + tid, row = u >> 6, c16 = u & 63;
            uint4 v = *(const uint4*)(smem + row * 1024 + ((c16 ^ (row & 7)) * 16));
            *(uint4*)(go + (size_t)(mbase + row) * 1024 + c16 * 16) = v;
        }
    }
}

// ---------------- launch ----------------
extern "C" void kernel_launch(void* const* d_in, const int* in_sizes, int n_in,
                              void* d_out, int out_size) {
    // resolve inputs by size signature (identity under canonical order)
    int i_z = -1, i_tb = -1, i_w1 = -1, i_b1 = -1, i_g = -1, i_be = -1, i_w2 = -1, i_b2 = -1;
    for (int i = 0; i < n_in; i++) {
        int s = in_sizes[i];
        if      (s == 4194304 && i_z  < 0) i_z  = i;
        else if (s == 393216  && i_tb < 0) i_tb = i;
        else if (s == 131072) { if (i_w1 < 0) i_w1 = i; else if (i_w2 < 0) i_w2 = i; }
        else if (s == 512)    { if (i_b1 < 0) i_b1 = i; else if (i_g < 0) i_g = i; else if (i_be < 0) i_be = i; }
        else if (s == 256     && i_b2 < 0) i_b2 = i;
    }
    if (i_z < 0 || i_tb < 0 || i_w1 < 0 || i_b1 < 0 || i_g < 0 || i_be < 0 || i_w2 < 0 || i_b2 < 0) {
        i_z = 0; i_tb = 1; i_w1 = 2; i_b1 = 3; i_g = 4; i_be = 5; i_w2 = 6; i_b2 = 7;
    }
    const float* z     = (const float*)d_in[i_z];
    const void*  tbl   = d_in[i_tb];
    const float* W1    = (const float*)d_in[i_w1];
    const float* b1    = (const float*)d_in[i_b1];
    const float* gamma = (const float*)d_in[i_g];
    const float* beta  = (const float*)d_in[i_be];
    const float* W2    = (const float*)d_in[i_w2];
    const float* b2    = (const float*)d_in[i_b2];
    float* out = (float*)d_out;

    cudaFuncSetAttribute(gemmY_kernel,  cudaFuncAttributeMaxDynamicSharedMemorySize, GY_DYN);
    cudaFuncSetAttribute(bnstat_kernel, cudaFuncAttributeMaxDynamicSharedMemorySize, ST_DYN);
    cudaFuncSetAttribute(gemm2_kernel,  cudaFuncAttributeMaxDynamicSharedMemorySize, G2_DYN);

    prepw_kernel<<<D_HID + D_OUT, 256>>>(W1, W2);
    prepz_kernel<<<16384 / 8, 256>>>(z);
    gemmY_kernel<<<dim3(4, 128), 256, GY_DYN>>>(b1);
    bnstat_kernel<<<512, 256, ST_DYN>>>(tbl);
    bnfin_kernel<<<1, 512>>>(gamma, beta);
    gemm2_kernel<<<2048, 256, G2_DYN>>>(tbl, b2, out);
}